// round 6
// baseline (speedup 1.0000x reference)
#include <cuda_runtime.h>
#include <cuda_bf16.h>
#include <cstddef>

// ---------------- problem constants ----------------
#define NGg    8
#define NVv    400
#define NCL    1200
#define KLIT   5
#define NNG    (2 * NVv + NCL)
#define D      128
#define LROWS  (NGg * 2 * NVv)        // 6400
#define CROWS  (NGg * NCL)            // 9600
#define NEDGE  (NGg * NCL * KLIT)     // 48000
#define EPG    (NCL * KLIT)
#define ROUNDS 26
#define ADJW   40

typedef __nv_bfloat16 bf16;

// smem layout: [0, WOFF) = X / As / gbuf region;  [WOFF, ...) = weights
#define WOFF   50176                  // 64*196*4 (lit-gate A tile)
#define SMEMSZ (WOFF + 3 * 128 * 68 * 4)   // + 3 MLP layers = 154624 B

// ---------------- device scratch ----------------
__device__ bf16  d_hl[2][LROWS * D];
__device__ bf16  d_hc[2][CROWS * D];
__device__ float d_cl[LROWS * D];
__device__ float d_cc[CROWS * D];
__device__ bf16  d_msg[CROWS * D];
__device__ bf16  d_wb[524288];
__device__ int   d_esrc[NEDGE];
__device__ int   d_adj[LROWS * ADJW];
__device__ int   d_deg[LROWS];
__device__ float d_vrow[LROWS];
__device__ volatile unsigned g_phase;
__device__ unsigned g_count;

#define WB_LMSG   0
#define WB_CMSG   49152
#define WB_CUWIH  98304
#define WB_CUWHH  163840
#define WB_LUWIH  229376
#define WB_LUWHH  360448
#define WB_VOTE0  425984
#define WB_VOTE1  442368

// ---------------- helpers ----------------
__device__ __forceinline__ void mma_bf16(float c[4],
    unsigned a0, unsigned a1, unsigned a2, unsigned a3, unsigned b0, unsigned b1)
{
    asm volatile(
        "mma.sync.aligned.m16n8k16.row.col.f32.bf16.bf16.f32 "
        "{%0,%1,%2,%3}, {%4,%5,%6,%7}, {%8,%9}, {%0,%1,%2,%3};"
        : "+f"(c[0]), "+f"(c[1]), "+f"(c[2]), "+f"(c[3])
        : "r"(a0), "r"(a1), "r"(a2), "r"(a3), "r"(b0), "r"(b1));
}
__device__ __forceinline__ float sigm(float x) { return 1.f / (1.f + expf(-x)); }
__device__ __forceinline__ int fliprow(int r) {
    int local = r % (2 * NVv);
    return r - local + ((local < NVv) ? local + NVv : local - NVv);
}
__device__ __forceinline__ unsigned pack_bf(float lo, float hi) {
    __nv_bfloat162 p = __floats2bfloat162_rn(lo, hi);
    return *(unsigned*)&p;
}

// grid barrier (all blocks resident by construction)
__device__ __forceinline__ void gsync(int nblk)
{
    __syncthreads();
    if (threadIdx.x == 0) {
        __threadfence();
        unsigned p = g_phase;
        unsigned t = atomicAdd(&g_count, 1u);
        if (t == (unsigned)nblk - 1u) {
            g_count = 0u;
            __threadfence();
            g_phase = p + 1u;
        } else {
            while (g_phase == p) __nanosleep(64);
            __threadfence();
        }
    }
    __syncthreads();
}

// ---------------- one-time setup kernels ----------------
__global__ void cvt_w(const float* __restrict__ s, bf16* __restrict__ dst, int n)
{
    int i = blockIdx.x * 256 + threadIdx.x;
    if (i < n) dst[i] = __float2bfloat16_rn(s[i]);
}

__global__ void init_hc(const float* __restrict__ Lw, const float* __restrict__ Lb,
                        const float* __restrict__ Cw, const float* __restrict__ Cb,
                        bf16* __restrict__ hl, bf16* __restrict__ hc,
                        float* __restrict__ cl, float* __restrict__ cc)
{
    int r = blockIdx.x, d = threadIdx.x;
    if (r < LROWS) {
        hl[(size_t)r * D + d] = __float2bfloat16_rn(Lw[d] + Lb[d]);
        cl[(size_t)r * D + d] = 0.f;
    }
    hc[(size_t)r * D + d] = __float2bfloat16_rn(Cw[d] + Cb[d]);
    cc[(size_t)r * D + d] = 0.f;
}

__global__ void compact_edges(const int* __restrict__ edge_src, int* __restrict__ esrc)
{
    int e = blockIdx.x * 256 + threadIdx.x;
    if (e < NEDGE) {
        int g = edge_src[e];
        esrc[e] = (g / NNG) * (2 * NVv) + (g % NNG);
    }
}

__global__ void build_adj(const int* __restrict__ esrc,
                          int* __restrict__ adj, int* __restrict__ deg)
{
    int lit = blockIdx.x * 160 + threadIdx.x;
    int g = lit / (2 * NVv);
    const int* es = esrc + g * EPG;
    int cnt = 0;
    for (int j = 0; j < EPG; j++) {
        if (es[j] == lit) {
            if (cnt < ADJW) adj[lit * ADJW + cnt] = g * NCL + j / KLIT;
            cnt++;
        }
    }
    deg[lit] = cnt < ADJW ? cnt : ADJW;
}

// ---------------- MLP phase (device fn): W layers resident once per phase --------
__device__ void mlp_phase(
    const bf16* __restrict__ hin, const bf16* __restrict__ Wb,
    const float* __restrict__ B0, const float* __restrict__ B1,
    const float* __restrict__ B2,
    bf16* __restrict__ out, int ntiles, int NL, int relu_last,
    int bid, int nblk, unsigned char* sm)
{
    unsigned (*X)[68] = (unsigned(*)[68])sm;
    unsigned* Wall    = (unsigned*)(sm + WOFF);
    const int tid = threadIdx.x, lane = tid & 31, warp = tid >> 5;
    const int grp = lane >> 2, tig = lane & 3;

    for (int l = 0; l < NL; l++) {
        const bf16* W = Wb + l * D * D;
        unsigned (*Wsm)[68] = (unsigned(*)[68])(Wall + l * 128 * 68);
        #pragma unroll
        for (int t = 0; t < 8; t++) {
            int flat = tid + 256 * t;
            int n = flat >> 4, kb = flat & 15;
            *(uint4*)&Wsm[n][kb * 4] = *(const uint4*)(W + (size_t)n * D + kb * 8);
        }
    }
    __syncthreads();

    const float* Bl[3] = { B0, B1, B2 };
    for (int tile = bid; tile < ntiles; tile += nblk) {
        int bm = tile * 32;
        #pragma unroll
        for (int t = 0; t < 2; t++) {
            int flat = tid + 256 * t;
            int r = flat >> 4, kb = flat & 15;
            *(uint4*)&X[r][kb * 4] =
                __ldcg((const uint4*)(hin + (size_t)(bm + r) * D + kb * 8));
        }
        __syncthreads();
        for (int l = 0; l < NL; l++) {
            unsigned (*Wsm)[68] = (unsigned(*)[68])(Wall + l * 128 * 68);
            float acc[2][2][4];
            #pragma unroll
            for (int mi = 0; mi < 2; mi++)
                #pragma unroll
                for (int ni = 0; ni < 2; ni++)
                    #pragma unroll
                    for (int u = 0; u < 4; u++) acc[mi][ni][u] = 0.f;

            #pragma unroll
            for (int ks = 0; ks < 8; ks++) {
                int kk = ks * 8;
                unsigned a[2][4], b[2][2];
                #pragma unroll
                for (int mi = 0; mi < 2; mi++) {
                    int r = mi * 16 + grp;
                    a[mi][0] = X[r    ][kk + tig];
                    a[mi][1] = X[r + 8][kk + tig];
                    a[mi][2] = X[r    ][kk + tig + 4];
                    a[mi][3] = X[r + 8][kk + tig + 4];
                }
                #pragma unroll
                for (int ni = 0; ni < 2; ni++) {
                    int n = warp * 16 + ni * 8 + grp;
                    b[ni][0] = Wsm[n][kk + tig];
                    b[ni][1] = Wsm[n][kk + tig + 4];
                }
                #pragma unroll
                for (int mi = 0; mi < 2; mi++)
                    #pragma unroll
                    for (int ni = 0; ni < 2; ni++)
                        mma_bf16(acc[mi][ni], a[mi][0], a[mi][1], a[mi][2], a[mi][3],
                                 b[ni][0], b[ni][1]);
            }
            __syncthreads();

            const float* B = Bl[l];
            int do_relu = (l < NL - 1) || relu_last;
            #pragma unroll
            for (int mi = 0; mi < 2; mi++) {
                #pragma unroll
                for (int ni = 0; ni < 2; ni++) {
                    int r0 = mi * 16 + grp;
                    int c0 = warp * 16 + ni * 8 + 2 * tig;
                    #pragma unroll
                    for (int h = 0; h < 2; h++) {
                        int r = r0 + h * 8;
                        float v0 = acc[mi][ni][h * 2 + 0] + B[c0];
                        float v1 = acc[mi][ni][h * 2 + 1] + B[c0 + 1];
                        if (do_relu) { v0 = fmaxf(v0, 0.f); v1 = fmaxf(v1, 0.f); }
                        unsigned p = pack_bf(v0, v1);
                        if (l == NL - 1)
                            *(unsigned*)(out + (size_t)(bm + r) * D + c0) = p;
                        else
                            X[r][c0 >> 1] = p;
                    }
                }
            }
            __syncthreads();
        }
    }
}

// ---------------- gate phase (device fn): fused aggregation + GEMM + LSTM ----------
// MODE 0 (clause, KTOT=256): A = [sum5 msg | hold]
// MODE 1 (lit,    KTOT=384): A = [ELL-sum msg | hold(flip) | hold]
template<int KTOT, int MODE>
__device__ void gate_phase(
    const bf16* __restrict__ msg, const int* __restrict__ esrc,
    const int* __restrict__ adj, const int* __restrict__ deg,
    const bf16* __restrict__ hold,
    const bf16* __restrict__ Wih, int ldwih, const bf16* __restrict__ Whh,
    const float* __restrict__ bih, const float* __restrict__ bhh,
    bf16* __restrict__ hnew, float* __restrict__ cst,
    int nrowtiles, int bid, int nblk, unsigned char* sm)
{
    const int WPR = KTOT / 2 + 4;
    unsigned (*As)[WPR] = (unsigned(*)[WPR])sm;
    unsigned (*Ws)[WPR] = (unsigned(*)[WPR])(sm + WOFF);

    const int tid = threadIdx.x, lane = tid & 31, warp = tid >> 5;
    const int wr = warp & 1, wc = warp >> 1;
    const int grp = lane >> 2, tig = lane & 3;
    const int dd0 = (bid & 3) * 32;
    const int j0  = bid >> 2;
    const int nd  = (nblk + 3) >> 2;

    // W slice for this dd: 128 rows x KTOT, once per phase
    const int NW4 = 128 * KTOT / 8;
    #pragma unroll 4
    for (int t = 0; t < NW4 / 256; t++) {
        int flat = tid + 256 * t;
        int wrow = flat / (KTOT / 8);
        int kb   = flat % (KTOT / 8);
        int n = (wrow >> 5) * 128 + dd0 + (wrow & 31);
        int k = kb * 8;
        uint4 v = (k < KTOT - 128)
            ? *(const uint4*)(Wih + (size_t)n * ldwih + k)
            : *(const uint4*)(Whh + (size_t)n * D + (k - (KTOT - 128)));
        *(uint4*)&Ws[wrow][kb * 4] = v;
    }
    __syncthreads();

    for (int j = j0; j < nrowtiles; j += nd) {
        int bm = j * 64;
        // ---- build A tile in smem ----
        if (MODE == 0) {
            #pragma unroll
            for (int t = 0; t < 16; t++) {
                int flat = tid + 256 * t;
                int r = flat >> 6, w = flat & 63;
                const int* es = esrc + (size_t)(bm + r) * KLIT;
                float s0 = 0.f, s1 = 0.f;
                #pragma unroll
                for (int e = 0; e < KLIT; e++) {
                    __nv_bfloat162 m =
                        __ldcg((const __nv_bfloat162*)(msg + (size_t)es[e] * D + w * 2));
                    s0 += __bfloat162float(m.x);
                    s1 += __bfloat162float(m.y);
                }
                As[r][w] = pack_bf(s0, s1);
            }
            #pragma unroll
            for (int t = 0; t < 4; t++) {
                int flat = tid + 256 * t;
                int r = flat >> 4, kb = flat & 15;
                *(uint4*)&As[r][64 + kb * 4] =
                    __ldcg((const uint4*)(hold + (size_t)(bm + r) * D + kb * 8));
            }
        } else {
            #pragma unroll
            for (int t = 0; t < 16; t++) {
                int flat = tid + 256 * t;
                int r = flat >> 6, w = flat & 63;
                int row = bm + r;
                int n = deg[row];
                const int* ad = adj + (size_t)row * ADJW;
                float s0 = 0.f, s1 = 0.f;
                for (int e = 0; e < n; e++) {
                    __nv_bfloat162 m =
                        __ldcg((const __nv_bfloat162*)(msg + (size_t)ad[e] * D + w * 2));
                    s0 += __bfloat162float(m.x);
                    s1 += __bfloat162float(m.y);
                }
                As[r][w] = pack_bf(s0, s1);
            }
            #pragma unroll
            for (int t = 0; t < 8; t++) {
                int flat = tid + 256 * t;
                int r = flat >> 5, kb = flat & 31;
                int row = bm + r;
                int k = 128 + kb * 8;
                const bf16* src = (k < 256)
                    ? hold + (size_t)fliprow(row) * D + (k - 128)
                    : hold + (size_t)row * D + (k - 256);
                *(uint4*)&As[r][64 + kb * 4] = __ldcg((const uint4*)src);
            }
        }
        __syncthreads();

        // ---- GEMM ----
        float acc[2][4][4];
        #pragma unroll
        for (int mi = 0; mi < 2; mi++)
            #pragma unroll
            for (int ni = 0; ni < 4; ni++)
                #pragma unroll
                for (int u = 0; u < 4; u++) acc[mi][ni][u] = 0.f;

        #pragma unroll
        for (int ks = 0; ks < KTOT / 16; ks++) {
            unsigned a[2][4], b[4][2];
            #pragma unroll
            for (int mi = 0; mi < 2; mi++) {
                int r = wr * 32 + mi * 16 + grp;
                a[mi][0] = As[r    ][ks * 8 + tig];
                a[mi][1] = As[r + 8][ks * 8 + tig];
                a[mi][2] = As[r    ][ks * 8 + tig + 4];
                a[mi][3] = As[r + 8][ks * 8 + tig + 4];
            }
            #pragma unroll
            for (int ni = 0; ni < 4; ni++) {
                int n = wc * 32 + ni * 8 + grp;
                b[ni][0] = Ws[n][ks * 8 + tig];
                b[ni][1] = Ws[n][ks * 8 + tig + 4];
            }
            #pragma unroll
            for (int mi = 0; mi < 2; mi++)
                #pragma unroll
                for (int ni = 0; ni < 4; ni++)
                    mma_bf16(acc[mi][ni], a[mi][0], a[mi][1], a[mi][2], a[mi][3],
                             b[ni][0], b[ni][1]);
        }
        __syncthreads();

        // ---- stage gates + LSTM epilogue ----
        float (*gbuf)[132] = (float(*)[132])sm;
        #pragma unroll
        for (int mi = 0; mi < 2; mi++) {
            #pragma unroll
            for (int ni = 0; ni < 4; ni++) {
                int r0 = wr * 32 + mi * 16 + grp;
                int c0 = wc * 32 + ni * 8 + 2 * tig;
                gbuf[r0    ][c0    ] = acc[mi][ni][0];
                gbuf[r0    ][c0 + 1] = acc[mi][ni][1];
                gbuf[r0 + 8][c0    ] = acc[mi][ni][2];
                gbuf[r0 + 8][c0 + 1] = acc[mi][ni][3];
            }
        }
        __syncthreads();

        int ddl = tid & 31;
        int rl0 = tid >> 5;
        int dd  = dd0 + ddl;
        float bi0 = bih[0 * 128 + dd] + bhh[0 * 128 + dd];
        float bi1 = bih[1 * 128 + dd] + bhh[1 * 128 + dd];
        float bi2 = bih[2 * 128 + dd] + bhh[2 * 128 + dd];
        float bi3 = bih[3 * 128 + dd] + bhh[3 * 128 + dd];
        #pragma unroll
        for (int it = 0; it < 8; it++) {
            int lrow = it * 8 + rl0;
            int row  = bm + lrow;
            float gi = gbuf[lrow][0 * 32 + ddl] + bi0;
            float gf = gbuf[lrow][1 * 32 + ddl] + bi1;
            float gg = gbuf[lrow][2 * 32 + ddl] + bi2;
            float go = gbuf[lrow][3 * 32 + ddl] + bi3;
            size_t off = (size_t)row * D + dd;
            float c2 = sigm(gf) * cst[off] + sigm(gi) * tanhf(gg);
            cst[off] = c2;
            hnew[off] = __float2bfloat16_rn(sigm(go) * tanhf(c2));
        }
        __syncthreads();
    }
}

// ---------------- persistent megakernel ----------------
__global__ __launch_bounds__(256, 1) void mega(
    const bf16* __restrict__ wb, const int* __restrict__ esrc,
    const int* __restrict__ adj, const int* __restrict__ deg,
    bf16* hl0, bf16* hl1, bf16* hc0, bf16* hc1,
    float* cl, float* cc, bf16* msg,
    const float* lmsg_b, const float* cmsg_b,
    const float* cu_bih, const float* cu_bhh,
    const float* lu_bih, const float* lu_bhh,
    const float* vote_b0, const float* vote_b1,
    const float* vote_w2, const float* vote_b2,
    const int* n_vars, float* vrow, float* out, int nblk)
{
    extern __shared__ __align__(16) unsigned char sm[];
    const int bid = blockIdx.x;
    bf16* hls[2] = { hl0, hl1 };
    bf16* hcs[2] = { hc0, hc1 };

    for (int r = 0; r < ROUNDS; r++) {
        bf16* hlc = hls[r & 1];
        bf16* hln = hls[(r + 1) & 1];
        bf16* hcc = hcs[r & 1];
        bf16* hcn = hcs[(r + 1) & 1];

        mlp_phase(hlc, wb + WB_LMSG, lmsg_b, lmsg_b + 128, lmsg_b + 256,
                  msg, LROWS / 32, 3, 0, bid, nblk, sm);
        gsync(nblk);
        gate_phase<256, 0>(msg, esrc, nullptr, nullptr, hcc,
                           wb + WB_CUWIH, D, wb + WB_CUWHH,
                           cu_bih, cu_bhh, hcn, cc, CROWS / 64, bid, nblk, sm);
        gsync(nblk);
        mlp_phase(hcn, wb + WB_CMSG, cmsg_b, cmsg_b + 128, cmsg_b + 256,
                  msg, CROWS / 32, 3, 0, bid, nblk, sm);
        gsync(nblk);
        gate_phase<384, 1>(msg, nullptr, adj, deg, hlc,
                           wb + WB_LUWIH, 2 * D, wb + WB_LUWHH,
                           lu_bih, lu_bhh, hln, cl, LROWS / 64, bid, nblk, sm);
        gsync(nblk);
    }

    // vote head
    bf16* hfin = hls[ROUNDS & 1];
    mlp_phase(hfin, wb + WB_VOTE0, vote_b0, vote_b1, vote_b1,
              msg, LROWS / 32, 2, 1, bid, nblk, sm);
    gsync(nblk);

    // per-row dot with vote_w2
    {
        int lane = threadIdx.x & 31;
        int gw = bid * 8 + (threadIdx.x >> 5);
        int nw = nblk * 8;
        for (int row = gw; row < LROWS; row += nw) {
            float s = 0.f;
            for (int w = lane; w < 64; w += 32) {
                __nv_bfloat162 m =
                    __ldcg((const __nv_bfloat162*)(msg + (size_t)row * D + w * 2));
                s += __bfloat162float(m.x) * vote_w2[w * 2]
                   + __bfloat162float(m.y) * vote_w2[w * 2 + 1];
            }
            #pragma unroll
            for (int sh = 16; sh > 0; sh >>= 1) s += __shfl_down_sync(0xffffffff, s, sh);
            if (lane == 0) vrow[row] = s + vote_b2[0];
        }
    }
    gsync(nblk);

    // per-graph mean
    if (bid == 0 && threadIdx.x < 256) {
        int warp = threadIdx.x >> 5;
        int lane = threadIdx.x & 31;
        if (warp < NGg) {
            float s = 0.f;
            for (int i = lane; i < 2 * NVv; i += 32)
                s += __ldcg(vrow + warp * (2 * NVv) + i);
            #pragma unroll
            for (int sh = 16; sh > 0; sh >>= 1) s += __shfl_down_sync(0xffffffff, s, sh);
            if (lane == 0) out[warp] = s / (2.f * (float)n_vars[warp]);
        }
    }
}

// ---------------- host orchestration ----------------
extern "C" void kernel_launch(void* const* d_in, const int* in_sizes, int n_in,
                              void* d_out, int out_size)
{
    const int* edge_src   = (const int*)d_in[0];
    const int* n_vars     = (const int*)d_in[6];
    const float* L_init_w = (const float*)d_in[7];
    const float* L_init_b = (const float*)d_in[8];
    const float* C_init_w = (const float*)d_in[9];
    const float* C_init_b = (const float*)d_in[10];
    const float* lmsg_w   = (const float*)d_in[11];
    const float* lmsg_b   = (const float*)d_in[12];
    const float* cmsg_w   = (const float*)d_in[13];
    const float* cmsg_b   = (const float*)d_in[14];
    const float* lu_wih   = (const float*)d_in[15];
    const float* lu_whh   = (const float*)d_in[16];
    const float* lu_bih   = (const float*)d_in[17];
    const float* lu_bhh   = (const float*)d_in[18];
    const float* cu_wih   = (const float*)d_in[19];
    const float* cu_whh   = (const float*)d_in[20];
    const float* cu_bih   = (const float*)d_in[21];
    const float* cu_bhh   = (const float*)d_in[22];
    const float* vote_w0  = (const float*)d_in[23];
    const float* vote_b0  = (const float*)d_in[24];
    const float* vote_w1  = (const float*)d_in[25];
    const float* vote_b1  = (const float*)d_in[26];
    const float* vote_w2  = (const float*)d_in[27];
    const float* vote_b2  = (const float*)d_in[28];

    bf16 *hl0, *hl1, *hc0, *hc1, *msg, *wb;
    float *cl, *cc, *vrow;
    int *esrc, *adj, *deg;
    cudaGetSymbolAddress((void**)&hl0,  d_hl);      hl1 = hl0 + LROWS * D;
    cudaGetSymbolAddress((void**)&hc0,  d_hc);      hc1 = hc0 + CROWS * D;
    cudaGetSymbolAddress((void**)&cl,   d_cl);
    cudaGetSymbolAddress((void**)&cc,   d_cc);
    cudaGetSymbolAddress((void**)&msg,  d_msg);
    cudaGetSymbolAddress((void**)&wb,   d_wb);
    cudaGetSymbolAddress((void**)&esrc, d_esrc);
    cudaGetSymbolAddress((void**)&adj,  d_adj);
    cudaGetSymbolAddress((void**)&deg,  d_deg);
    cudaGetSymbolAddress((void**)&vrow, d_vrow);

    cudaFuncSetAttribute(mega, cudaFuncAttributeMaxDynamicSharedMemorySize, SMEMSZ);

    int nsm = 0;
    cudaDeviceGetAttribute(&nsm, cudaDevAttrMultiProcessorCount, 0);
    if (nsm <= 0) nsm = 148;

    // one-time weight conversion
    cvt_w<<<(3 * 16384 + 255) / 256, 256>>>(lmsg_w,  wb + WB_LMSG,  3 * 16384);
    cvt_w<<<(3 * 16384 + 255) / 256, 256>>>(cmsg_w,  wb + WB_CMSG,  3 * 16384);
    cvt_w<<<(65536 + 255) / 256, 256>>>(cu_wih, wb + WB_CUWIH, 65536);
    cvt_w<<<(65536 + 255) / 256, 256>>>(cu_whh, wb + WB_CUWHH, 65536);
    cvt_w<<<(131072 + 255) / 256, 256>>>(lu_wih, wb + WB_LUWIH, 131072);
    cvt_w<<<(65536 + 255) / 256, 256>>>(lu_whh, wb + WB_LUWHH, 65536);
    cvt_w<<<(16384 + 255) / 256, 256>>>(vote_w0, wb + WB_VOTE0, 16384);
    cvt_w<<<(16384 + 255) / 256, 256>>>(vote_w1, wb + WB_VOTE1, 16384);

    compact_edges<<<(NEDGE + 255) / 256, 256>>>(edge_src, esrc);
    init_hc<<<CROWS, D>>>(L_init_w, L_init_b, C_init_w, C_init_b, hl0, hc0, cl, cc);
    build_adj<<<LROWS / 160, 160>>>(esrc, adj, deg);

    mega<<<nsm, 256, SMEMSZ>>>(
        wb, esrc, adj, deg, hl0, hl1, hc0, hc1, cl, cc, msg,
        lmsg_b, cmsg_b, cu_bih, cu_bhh, lu_bih, lu_bhh,
        vote_b0, vote_b1, vote_w2, vote_b2,
        n_vars, vrow, (float*)d_out, nsm);

    (void)in_sizes; (void)n_in; (void)out_size;
}

// round 7
// speedup vs baseline: 1.5950x; 1.5950x over previous
#include <cuda_runtime.h>
#include <cuda_bf16.h>
#include <cstddef>

// ---------------- problem constants ----------------
#define NGg    8
#define NVv    400
#define NCL    1200
#define KLIT   5
#define NNG    (2 * NVv + NCL)
#define D      128
#define LROWS  (NGg * 2 * NVv)        // 6400
#define CROWS  (NGg * NCL)            // 9600
#define NEDGE  (NGg * NCL * KLIT)     // 48000
#define EPG    (NCL * KLIT)
#define ROUNDS 26
#define ADJW   40

typedef __nv_bfloat16 bf16;

// ---------------- device scratch ----------------
__device__ bf16  d_hl[2][LROWS * D];
__device__ bf16  d_hc[2][CROWS * D];
__device__ float d_cl[LROWS * D];
__device__ float d_cc[CROWS * D];
__device__ bf16  d_msg[CROWS * D];
__device__ bf16  d_wb[524288];
__device__ int   d_esrc[NEDGE];
__device__ int   d_adj[LROWS * ADJW];
__device__ int   d_deg[LROWS];
__device__ float d_vrow[LROWS];

// contiguous weight segments in d_wb (bf16 elems)
#define WB_LMSG   0         // 49152
#define WB_CMSG   49152     // 49152
#define WB_CUWIH  98304     // 65536
#define WB_CUWHH  163840    // 65536
#define WB_LUWIH  229376    // 131072
#define WB_LUWHH  360448    // 65536
#define WB_VOTE0  425984    // 16384
#define WB_VOTE1  442368    // 16384
#define WB_TOTAL  458752

// ---------------- helpers ----------------
__device__ __forceinline__ void mma_bf16(float c[4],
    unsigned a0, unsigned a1, unsigned a2, unsigned a3, unsigned b0, unsigned b1)
{
    asm volatile(
        "mma.sync.aligned.m16n8k16.row.col.f32.bf16.bf16.f32 "
        "{%0,%1,%2,%3}, {%4,%5,%6,%7}, {%8,%9}, {%0,%1,%2,%3};"
        : "+f"(c[0]), "+f"(c[1]), "+f"(c[2]), "+f"(c[3])
        : "r"(a0), "r"(a1), "r"(a2), "r"(a3), "r"(b0), "r"(b1));
}
__device__ __forceinline__ void cpasync16(void* smem, const void* g)
{
    unsigned a = (unsigned)__cvta_generic_to_shared(smem);
    asm volatile("cp.async.cg.shared.global [%0], [%1], 16;" :: "r"(a), "l"(g));
}
#define CP_COMMIT() asm volatile("cp.async.commit_group;")
#define CP_WAIT0()  asm volatile("cp.async.wait_group 0;")

__device__ __forceinline__ float sigm(float x) { return 1.f / (1.f + expf(-x)); }
__device__ __forceinline__ int fliprow(int r) {
    int local = r % (2 * NVv);
    return r - local + ((local < NVv) ? local + NVv : local - NVv);
}
__device__ __forceinline__ unsigned pack_bf(float lo, float hi) {
    __nv_bfloat162 p = __floats2bfloat162_rn(lo, hi);
    return *(unsigned*)&p;
}

// ---------------- one-time setup ----------------
__global__ void cvt_all(
    const float* __restrict__ lmsg_w, const float* __restrict__ cmsg_w,
    const float* __restrict__ cu_wih, const float* __restrict__ cu_whh,
    const float* __restrict__ lu_wih, const float* __restrict__ lu_whh,
    const float* __restrict__ vote_w0, const float* __restrict__ vote_w1,
    bf16* __restrict__ wb)
{
    int i = blockIdx.x * 256 + threadIdx.x;
    if (i >= WB_TOTAL) return;
    float v;
    if      (i < WB_CMSG)   v = lmsg_w[i - WB_LMSG];
    else if (i < WB_CUWIH)  v = cmsg_w[i - WB_CMSG];
    else if (i < WB_CUWHH)  v = cu_wih[i - WB_CUWIH];
    else if (i < WB_LUWIH)  v = cu_whh[i - WB_CUWHH];
    else if (i < WB_LUWHH)  v = lu_wih[i - WB_LUWIH];
    else if (i < WB_VOTE0)  v = lu_whh[i - WB_LUWHH];
    else if (i < WB_VOTE1)  v = vote_w0[i - WB_VOTE0];
    else                    v = vote_w1[i - WB_VOTE1];
    wb[i] = __float2bfloat16_rn(v);
}

__global__ void init_hc(const float* __restrict__ Lw, const float* __restrict__ Lb,
                        const float* __restrict__ Cw, const float* __restrict__ Cb,
                        bf16* __restrict__ hl, bf16* __restrict__ hc,
                        float* __restrict__ cl, float* __restrict__ cc)
{
    int r = blockIdx.x, d = threadIdx.x;
    if (r < LROWS) {
        hl[(size_t)r * D + d] = __float2bfloat16_rn(Lw[d] + Lb[d]);
        cl[(size_t)r * D + d] = 0.f;
    }
    hc[(size_t)r * D + d] = __float2bfloat16_rn(Cw[d] + Cb[d]);
    cc[(size_t)r * D + d] = 0.f;
}

__global__ void compact_edges(const int* __restrict__ edge_src, int* __restrict__ esrc)
{
    int e = blockIdx.x * 256 + threadIdx.x;
    if (e < NEDGE) {
        int g = edge_src[e];
        esrc[e] = (g / NNG) * (2 * NVv) + (g % NNG);
    }
}

__global__ void build_adj(const int* __restrict__ esrc,
                          int* __restrict__ adj, int* __restrict__ deg)
{
    int lit = blockIdx.x * 160 + threadIdx.x;
    int g = lit / (2 * NVv);
    const int* es = esrc + g * EPG;
    int cnt = 0;
    for (int j = 0; j < EPG; j++) {
        if (es[j] == lit) {
            if (cnt < ADJW) adj[lit * ADJW + cnt] = g * NCL + j / KLIT;
            cnt++;
        }
    }
    deg[lit] = cnt < ADJW ? cnt : ADJW;
}

// ---------------- fused MLP (bf16, cp.async W pipeline), BM=32, 256 thr -----------
#define MLP_SMEM ((32 * 68 + 2 * 128 * 68) * 4)
template<int NL>
__global__ __launch_bounds__(256) void mlp_fused(
    const bf16* __restrict__ hin,
    const bf16* __restrict__ W0, const float* __restrict__ B0,
    const bf16* __restrict__ W1, const float* __restrict__ B1,
    const bf16* __restrict__ W2, const float* __restrict__ B2,
    bf16* __restrict__ out, int relu_last)
{
    extern __shared__ __align__(16) unsigned char dynsmem[];
    unsigned (*X)[68] = (unsigned(*)[68])dynsmem;
    unsigned* Wbase   = (unsigned*)(dynsmem + 32 * 68 * 4);

    const int tid  = threadIdx.x;
    const int lane = tid & 31;
    const int warp = tid >> 5;
    const int grp  = lane >> 2;
    const int tig  = lane & 3;
    const int bm   = blockIdx.x * 32;

    const bf16* Wl[3] = { W0, W1, W2 };
    const float* Bl[3] = { B0, B1, B2 };

    {
        const bf16* W = Wl[0];
        #pragma unroll
        for (int t = 0; t < 8; t++) {
            int flat = tid + 256 * t;
            int n = flat >> 4, kb = flat & 15;
            cpasync16(Wbase + (size_t)n * 68 + kb * 4, W + (size_t)n * D + kb * 8);
        }
        CP_COMMIT();
    }
    #pragma unroll
    for (int t = 0; t < 2; t++) {
        int flat = tid + 256 * t;
        int r = flat >> 4, kb = flat & 15;
        uint4 v = *(const uint4*)(hin + (size_t)(bm + r) * D + kb * 8);
        *(uint4*)&X[r][kb * 4] = v;
    }

    for (int l = 0; l < NL; l++) {
        CP_WAIT0();
        __syncthreads();
        unsigned (*Wsm)[68] = (unsigned(*)[68])(Wbase + (l & 1) * 128 * 68);
        if (l + 1 < NL) {
            unsigned* nxt = Wbase + ((l + 1) & 1) * 128 * 68;
            const bf16* W = Wl[l + 1];
            #pragma unroll
            for (int t = 0; t < 8; t++) {
                int flat = tid + 256 * t;
                int n = flat >> 4, kb = flat & 15;
                cpasync16(nxt + (size_t)n * 68 + kb * 4, W + (size_t)n * D + kb * 8);
            }
            CP_COMMIT();
        }

        float acc[2][2][4];
        #pragma unroll
        for (int mi = 0; mi < 2; mi++)
            #pragma unroll
            for (int ni = 0; ni < 2; ni++)
                #pragma unroll
                for (int u = 0; u < 4; u++) acc[mi][ni][u] = 0.f;

        #pragma unroll
        for (int ks = 0; ks < 8; ks++) {
            int kk = ks * 8;
            unsigned a[2][4], b[2][2];
            #pragma unroll
            for (int mi = 0; mi < 2; mi++) {
                int r = mi * 16 + grp;
                a[mi][0] = X[r    ][kk + tig];
                a[mi][1] = X[r + 8][kk + tig];
                a[mi][2] = X[r    ][kk + tig + 4];
                a[mi][3] = X[r + 8][kk + tig + 4];
            }
            #pragma unroll
            for (int ni = 0; ni < 2; ni++) {
                int n = warp * 16 + ni * 8 + grp;
                b[ni][0] = Wsm[n][kk + tig];
                b[ni][1] = Wsm[n][kk + tig + 4];
            }
            #pragma unroll
            for (int mi = 0; mi < 2; mi++)
                #pragma unroll
                for (int ni = 0; ni < 2; ni++)
                    mma_bf16(acc[mi][ni], a[mi][0], a[mi][1], a[mi][2], a[mi][3],
                             b[ni][0], b[ni][1]);
        }
        __syncthreads();

        const float* B = Bl[l];
        int do_relu = (l < NL - 1) || relu_last;
        #pragma unroll
        for (int mi = 0; mi < 2; mi++) {
            #pragma unroll
            for (int ni = 0; ni < 2; ni++) {
                int r0 = mi * 16 + grp;
                int c0 = warp * 16 + ni * 8 + 2 * tig;
                #pragma unroll
                for (int h = 0; h < 2; h++) {
                    int r = r0 + h * 8;
                    float v0 = acc[mi][ni][h * 2 + 0] + B[c0];
                    float v1 = acc[mi][ni][h * 2 + 1] + B[c0 + 1];
                    if (do_relu) { v0 = fmaxf(v0, 0.f); v1 = fmaxf(v1, 0.f); }
                    unsigned p = pack_bf(v0, v1);
                    if (l == NL - 1)
                        *(unsigned*)(out + (size_t)(bm + r) * D + c0) = p;
                    else
                        X[r][c0 >> 1] = p;
                }
            }
        }
    }
}

// ---------------- fused gate: smem aggregation prologue + GEMM + LSTM epilogue -----
// MODE 0 (clause, KTOT=256): A = [sum5 msg | hold]
// MODE 1 (lit,    KTOT=384): A = [ELL-sum msg | hold(flip) | hold]
// smem: aggbuf[64][68] words (17408 B) + 2 stages of (As 64x36 + Ws 128x36) (55296 B)
#define AGGSZ      (64 * 68 * 4)
#define GATE_STAGE ((64 * 36 + 128 * 36) * 4)
#define GATE_SMEM  (AGGSZ + 2 * GATE_STAGE)
template<int KTOT, int MODE>
__global__ __launch_bounds__(256) void gate_lstm(
    const bf16* __restrict__ msg, const int* __restrict__ esrc,
    const int* __restrict__ adj, const int* __restrict__ deg,
    const bf16* __restrict__ hold,
    const bf16* __restrict__ Wih, int ldwih,
    const bf16* __restrict__ Whh,
    const float* __restrict__ bih, const float* __restrict__ bhh,
    bf16* __restrict__ hnew, float* __restrict__ cst)
{
    extern __shared__ __align__(16) unsigned char dynsmem[];
    unsigned (*aggbuf)[68] = (unsigned(*)[68])dynsmem;

    const int tid  = threadIdx.x;
    const int lane = tid & 31;
    const int warp = tid >> 5;
    const int wr   = warp & 1;
    const int wc   = warp >> 1;
    const int grp  = lane >> 2;
    const int tig  = lane & 3;
    const int bm   = blockIdx.x * 64;
    const int dd0  = blockIdx.y * 32;

    // ---- aggregation prologue: 64 rows x 64 word-slots ----
    if (MODE == 0) {
        #pragma unroll
        for (int t = 0; t < 16; t++) {
            int flat = tid + 256 * t;
            int r = flat >> 6, w = flat & 63;
            const int* es = esrc + (size_t)(bm + r) * KLIT;
            float s0 = 0.f, s1 = 0.f;
            #pragma unroll
            for (int e = 0; e < KLIT; e++) {
                __nv_bfloat162 m =
                    *(const __nv_bfloat162*)(msg + (size_t)es[e] * D + w * 2);
                s0 += __bfloat162float(m.x);
                s1 += __bfloat162float(m.y);
            }
            aggbuf[r][w] = pack_bf(s0, s1);
        }
    } else {
        #pragma unroll
        for (int t = 0; t < 16; t++) {
            int flat = tid + 256 * t;
            int r = flat >> 6, w = flat & 63;
            int row = bm + r;
            int n = deg[row];
            const int* ad = adj + (size_t)row * ADJW;
            float s0 = 0.f, s1 = 0.f;
            for (int e = 0; e < n; e++) {
                __nv_bfloat162 m =
                    *(const __nv_bfloat162*)(msg + (size_t)ad[e] * D + w * 2);
                s0 += __bfloat162float(m.x);
                s1 += __bfloat162float(m.y);
            }
            aggbuf[r][w] = pack_bf(s0, s1);
        }
    }

    // ---- double-buffered k-loop ----
    auto ldA = [&](int ch, int t) -> uint4 {         // only for k0 >= 128
        int k0 = ch * 64;
        int flat = tid + 256 * t;
        int lr = flat >> 3, kb = flat & 7;
        int row = bm + lr;
        int k = k0 + kb * 8;
        if (MODE == 0) {
            return *(const uint4*)(hold + (size_t)row * D + (k - 128));
        } else {
            if (k < 256) return *(const uint4*)(hold + (size_t)fliprow(row) * D + (k - 128));
            else         return *(const uint4*)(hold + (size_t)row * D + (k - 256));
        }
    };
    auto ldW = [&](int ch, int t) -> uint4 {
        int k0 = ch * 64;
        int flat = tid + 256 * t;
        int wrow = flat >> 3, kb = flat & 7;
        int n = (wrow >> 5) * 128 + dd0 + (wrow & 31);
        int k = k0 + kb * 8;
        if (k0 < KTOT - 128) return *(const uint4*)(Wih + (size_t)n * ldwih + k);
        else                 return *(const uint4*)(Whh + (size_t)n * D + (k - (KTOT - 128)));
    };
    auto stA = [&](int st, int t, uint4 v) {
        unsigned (*As)[36] = (unsigned(*)[36])(dynsmem + AGGSZ + st * GATE_STAGE);
        int flat = tid + 256 * t;
        int lr = flat >> 3, kb = flat & 7;
        *(uint4*)&As[lr][kb * 4] = v;
    };
    auto stW = [&](int st, int t, uint4 v) {
        unsigned (*Ws)[36] = (unsigned(*)[36])(dynsmem + AGGSZ + st * GATE_STAGE + 64 * 36 * 4);
        int flat = tid + 256 * t;
        int wrow = flat >> 3, kb = flat & 7;
        *(uint4*)&Ws[wrow][kb * 4] = v;
    };

    float acc[2][4][4];
    #pragma unroll
    for (int mi = 0; mi < 2; mi++)
        #pragma unroll
        for (int ni = 0; ni < 4; ni++)
            #pragma unroll
            for (int u = 0; u < 4; u++) acc[mi][ni][u] = 0.f;

    const int NCH = KTOT / 64;
    #pragma unroll
    for (int t = 0; t < 4; t++) stW(0, t, ldW(0, t));
    __syncthreads();                                  // covers aggbuf + W stage 0

    #pragma unroll
    for (int ch = 0; ch < NCH; ch++) {
        const int st = ch & 1;
        const int k0 = ch * 64;
        const bool more  = (ch + 1 < NCH);
        const bool nextA = more && ((ch + 1) * 64 >= 128);
        uint4 pw[4], pa[2];
        if (more) {
            #pragma unroll
            for (int t = 0; t < 4; t++) pw[t] = ldW(ch + 1, t);
            if (nextA) {
                #pragma unroll
                for (int t = 0; t < 2; t++) pa[t] = ldA(ch + 1, t);
            }
        }
        unsigned (*As)[36] = (unsigned(*)[36])(dynsmem + AGGSZ + st * GATE_STAGE);
        unsigned (*Ws)[36] = (unsigned(*)[36])(dynsmem + AGGSZ + st * GATE_STAGE + 64 * 36 * 4);
        #pragma unroll
        for (int ks = 0; ks < 4; ks++) {
            unsigned a[2][4], b[4][2];
            if (k0 < 128) {
                int bw = (k0 >> 1) + ks * 8;
                #pragma unroll
                for (int mi = 0; mi < 2; mi++) {
                    int r = wr * 32 + mi * 16 + grp;
                    a[mi][0] = aggbuf[r    ][bw + tig];
                    a[mi][1] = aggbuf[r + 8][bw + tig];
                    a[mi][2] = aggbuf[r    ][bw + tig + 4];
                    a[mi][3] = aggbuf[r + 8][bw + tig + 4];
                }
            } else {
                #pragma unroll
                for (int mi = 0; mi < 2; mi++) {
                    int r = wr * 32 + mi * 16 + grp;
                    a[mi][0] = As[r    ][ks * 8 + tig];
                    a[mi][1] = As[r + 8][ks * 8 + tig];
                    a[mi][2] = As[r    ][ks * 8 + tig + 4];
                    a[mi][3] = As[r + 8][ks * 8 + tig + 4];
                }
            }
            #pragma unroll
            for (int ni = 0; ni < 4; ni++) {
                int n = wc * 32 + ni * 8 + grp;
                b[ni][0] = Ws[n][ks * 8 + tig];
                b[ni][1] = Ws[n][ks * 8 + tig + 4];
            }
            #pragma unroll
            for (int mi = 0; mi < 2; mi++)
                #pragma unroll
                for (int ni = 0; ni < 4; ni++)
                    mma_bf16(acc[mi][ni], a[mi][0], a[mi][1], a[mi][2], a[mi][3],
                             b[ni][0], b[ni][1]);
        }
        if (more) {
            #pragma unroll
            for (int t = 0; t < 4; t++) stW(1 - st, t, pw[t]);
            if (nextA) {
                #pragma unroll
                for (int t = 0; t < 2; t++) stA(1 - st, t, pa[t]);
            }
        }
        __syncthreads();
    }

    // ---- gates -> smem, LSTM epilogue ----
    float (*gbuf)[132] = (float(*)[132])(dynsmem + AGGSZ);
    #pragma unroll
    for (int mi = 0; mi < 2; mi++) {
        #pragma unroll
        for (int ni = 0; ni < 4; ni++) {
            int r0 = wr * 32 + mi * 16 + grp;
            int c0 = wc * 32 + ni * 8 + 2 * tig;
            gbuf[r0    ][c0    ] = acc[mi][ni][0];
            gbuf[r0    ][c0 + 1] = acc[mi][ni][1];
            gbuf[r0 + 8][c0    ] = acc[mi][ni][2];
            gbuf[r0 + 8][c0 + 1] = acc[mi][ni][3];
        }
    }
    __syncthreads();

    int ddl = tid & 31;
    int rl0 = tid >> 5;
    int dd  = dd0 + ddl;
    float bi0 = bih[0 * 128 + dd] + bhh[0 * 128 + dd];
    float bi1 = bih[1 * 128 + dd] + bhh[1 * 128 + dd];
    float bi2 = bih[2 * 128 + dd] + bhh[2 * 128 + dd];
    float bi3 = bih[3 * 128 + dd] + bhh[3 * 128 + dd];
    #pragma unroll
    for (int it = 0; it < 8; it++) {
        int lrow = it * 8 + rl0;
        int row  = bm + lrow;
        float gi = gbuf[lrow][0 * 32 + ddl] + bi0;
        float gf = gbuf[lrow][1 * 32 + ddl] + bi1;
        float gg = gbuf[lrow][2 * 32 + ddl] + bi2;
        float go = gbuf[lrow][3 * 32 + ddl] + bi3;
        size_t off = (size_t)row * D + dd;
        float c2 = sigm(gf) * cst[off] + sigm(gi) * tanhf(gg);
        cst[off] = c2;
        hnew[off] = __float2bfloat16_rn(sigm(go) * tanhf(c2));
    }
}

// ---------------- vote head ----------------
__global__ void vote_row(const bf16* __restrict__ v2, const float* __restrict__ w2,
                         const float* __restrict__ b2, float* __restrict__ vrow)
{
    int r = blockIdx.x, t = threadIdx.x;
    float p = __bfloat162float(v2[(size_t)r * D + t]) * w2[t];
    #pragma unroll
    for (int s = 16; s > 0; s >>= 1) p += __shfl_down_sync(0xffffffff, p, s);
    __shared__ float ws[4];
    if ((t & 31) == 0) ws[t >> 5] = p;
    __syncthreads();
    if (t == 0) vrow[r] = ws[0] + ws[1] + ws[2] + ws[3] + b2[0];
}

__global__ void graph_mean(const float* __restrict__ vrow, const int* __restrict__ n_vars,
                           float* __restrict__ out)
{
    int g = blockIdx.x, t = threadIdx.x;
    float s = 0.f;
    for (int i = t; i < 2 * NVv; i += 256) s += vrow[g * (2 * NVv) + i];
    __shared__ float red[256];
    red[t] = s;
    __syncthreads();
    for (int st = 128; st > 0; st >>= 1) {
        if (t < st) red[t] += red[t + st];
        __syncthreads();
    }
    if (t == 0) out[g] = red[0] / (2.f * (float)n_vars[g]);
}

// ---------------- host orchestration ----------------
extern "C" void kernel_launch(void* const* d_in, const int* in_sizes, int n_in,
                              void* d_out, int out_size)
{
    const int* edge_src   = (const int*)d_in[0];
    const int* n_vars     = (const int*)d_in[6];
    const float* L_init_w = (const float*)d_in[7];
    const float* L_init_b = (const float*)d_in[8];
    const float* C_init_w = (const float*)d_in[9];
    const float* C_init_b = (const float*)d_in[10];
    const float* lmsg_w   = (const float*)d_in[11];
    const float* lmsg_b   = (const float*)d_in[12];
    const float* cmsg_w   = (const float*)d_in[13];
    const float* cmsg_b   = (const float*)d_in[14];
    const float* lu_wih   = (const float*)d_in[15];
    const float* lu_whh   = (const float*)d_in[16];
    const float* lu_bih   = (const float*)d_in[17];
    const float* lu_bhh   = (const float*)d_in[18];
    const float* cu_wih   = (const float*)d_in[19];
    const float* cu_whh   = (const float*)d_in[20];
    const float* cu_bih   = (const float*)d_in[21];
    const float* cu_bhh   = (const float*)d_in[22];
    const float* vote_w0  = (const float*)d_in[23];
    const float* vote_b0  = (const float*)d_in[24];
    const float* vote_w1  = (const float*)d_in[25];
    const float* vote_b1  = (const float*)d_in[26];
    const float* vote_w2  = (const float*)d_in[27];
    const float* vote_b2  = (const float*)d_in[28];

    bf16 *hl0, *hl1, *hc0, *hc1, *msg, *wb;
    float *cl, *cc, *vrow;
    int *esrc, *adj, *deg;
    cudaGetSymbolAddress((void**)&hl0,  d_hl);      hl1 = hl0 + LROWS * D;
    cudaGetSymbolAddress((void**)&hc0,  d_hc);      hc1 = hc0 + CROWS * D;
    cudaGetSymbolAddress((void**)&cl,   d_cl);
    cudaGetSymbolAddress((void**)&cc,   d_cc);
    cudaGetSymbolAddress((void**)&msg,  d_msg);
    cudaGetSymbolAddress((void**)&wb,   d_wb);
    cudaGetSymbolAddress((void**)&esrc, d_esrc);
    cudaGetSymbolAddress((void**)&adj,  d_adj);
    cudaGetSymbolAddress((void**)&deg,  d_deg);
    cudaGetSymbolAddress((void**)&vrow, d_vrow);

    cudaFuncSetAttribute(mlp_fused<3>, cudaFuncAttributeMaxDynamicSharedMemorySize, MLP_SMEM);
    cudaFuncSetAttribute(mlp_fused<2>, cudaFuncAttributeMaxDynamicSharedMemorySize, MLP_SMEM);
    cudaFuncSetAttribute(gate_lstm<256, 0>, cudaFuncAttributeMaxDynamicSharedMemorySize, GATE_SMEM);
    cudaFuncSetAttribute(gate_lstm<384, 1>, cudaFuncAttributeMaxDynamicSharedMemorySize, GATE_SMEM);

    cvt_all<<<(WB_TOTAL + 255) / 256, 256>>>(lmsg_w, cmsg_w, cu_wih, cu_whh,
                                             lu_wih, lu_whh, vote_w0, vote_w1, wb);
    compact_edges<<<(NEDGE + 255) / 256, 256>>>(edge_src, esrc);
    init_hc<<<CROWS, D>>>(L_init_w, L_init_b, C_init_w, C_init_b, hl0, hc0, cl, cc);
    build_adj<<<LROWS / 160, 160>>>(esrc, adj, deg);

    bf16* hls[2] = { hl0, hl1 };
    bf16* hcs[2] = { hc0, hc1 };

    for (int r = 0; r < ROUNDS; r++) {
        bf16* hlc = hls[r & 1];
        bf16* hln = hls[(r + 1) & 1];
        bf16* hcc = hcs[r & 1];
        bf16* hcn = hcs[(r + 1) & 1];

        mlp_fused<3><<<LROWS / 32, 256, MLP_SMEM>>>(hlc,
            wb + WB_LMSG + 0 * D * D, lmsg_b + 0 * D,
            wb + WB_LMSG + 1 * D * D, lmsg_b + 1 * D,
            wb + WB_LMSG + 2 * D * D, lmsg_b + 2 * D, msg, 0);
        gate_lstm<256, 0><<<dim3(CROWS / 64, 4), 256, GATE_SMEM>>>(
            msg, esrc, nullptr, nullptr, hcc,
            wb + WB_CUWIH, D, wb + WB_CUWHH, cu_bih, cu_bhh, hcn, cc);
        mlp_fused<3><<<CROWS / 32, 256, MLP_SMEM>>>(hcn,
            wb + WB_CMSG + 0 * D * D, cmsg_b + 0 * D,
            wb + WB_CMSG + 1 * D * D, cmsg_b + 1 * D,
            wb + WB_CMSG + 2 * D * D, cmsg_b + 2 * D, msg, 0);
        gate_lstm<384, 1><<<dim3(LROWS / 64, 4), 256, GATE_SMEM>>>(
            msg, nullptr, adj, deg, hlc,
            wb + WB_LUWIH, 2 * D, wb + WB_LUWHH, lu_bih, lu_bhh, hln, cl);
    }

    bf16* hfin = hls[ROUNDS & 1];
    mlp_fused<2><<<LROWS / 32, 256, MLP_SMEM>>>(hfin,
        wb + WB_VOTE0, vote_b0, wb + WB_VOTE1, vote_b1, wb + WB_VOTE1, vote_b1, msg, 1);
    vote_row<<<LROWS, D>>>(msg, vote_w2, vote_b2, vrow);
    graph_mean<<<NGg, 256>>>(vrow, n_vars, (float*)d_out);

    (void)in_sizes; (void)n_in; (void)out_size;
}

// round 8
// speedup vs baseline: 1.8335x; 1.1495x over previous
#include <cuda_runtime.h>
#include <cuda_bf16.h>
#include <cstddef>

// ---------------- problem constants ----------------
#define NGg    8
#define NVv    400
#define NCL    1200
#define KLIT   5
#define NNG    (2 * NVv + NCL)
#define D      128
#define LROWS  (NGg * 2 * NVv)        // 6400
#define CROWS  (NGg * NCL)            // 9600
#define NEDGE  (NGg * NCL * KLIT)     // 48000
#define EPG    (NCL * KLIT)
#define ROUNDS 26
#define ADJW   40

typedef __nv_bfloat16 bf16;

// ---------------- device scratch ----------------
__device__ bf16  d_hl[2][LROWS * D];
__device__ bf16  d_hc[2][CROWS * D];
__device__ float d_cl[LROWS * D];
__device__ float d_cc[CROWS * D];
__device__ bf16  d_msg[CROWS * D];
__device__ bf16  d_agg[CROWS * D];
__device__ bf16  d_wb[524288];
__device__ int   d_esrc[NEDGE];
__device__ int   d_adj[LROWS * ADJW];
__device__ int   d_deg[LROWS];
__device__ float d_vrow[LROWS];

// contiguous weight segments in d_wb (bf16 elems)
#define WB_LMSG   0         // 49152
#define WB_CMSG   49152     // 49152
#define WB_CUWIH  98304     // 65536
#define WB_CUWHH  163840    // 65536
#define WB_LUWIH  229376    // 131072
#define WB_LUWHH  360448    // 65536
#define WB_VOTE0  425984    // 16384
#define WB_VOTE1  442368    // 16384
#define WB_TOTAL  458752

// ---------------- helpers ----------------
__device__ __forceinline__ void mma_bf16(float c[4],
    unsigned a0, unsigned a1, unsigned a2, unsigned a3, unsigned b0, unsigned b1)
{
    asm volatile(
        "mma.sync.aligned.m16n8k16.row.col.f32.bf16.bf16.f32 "
        "{%0,%1,%2,%3}, {%4,%5,%6,%7}, {%8,%9}, {%0,%1,%2,%3};"
        : "+f"(c[0]), "+f"(c[1]), "+f"(c[2]), "+f"(c[3])
        : "r"(a0), "r"(a1), "r"(a2), "r"(a3), "r"(b0), "r"(b1));
}
__device__ __forceinline__ void cpasync16(void* smem, const void* g)
{
    unsigned a = (unsigned)__cvta_generic_to_shared(smem);
    asm volatile("cp.async.cg.shared.global [%0], [%1], 16;" :: "r"(a), "l"(g));
}
#define CP_COMMIT() asm volatile("cp.async.commit_group;")
#define CP_WAIT0()  asm volatile("cp.async.wait_group 0;")

__device__ __forceinline__ float sigm(float x) { return 1.f / (1.f + expf(-x)); }
__device__ __forceinline__ int fliprow(int r) {
    int local = r % (2 * NVv);
    return r - local + ((local < NVv) ? local + NVv : local - NVv);
}
__device__ __forceinline__ unsigned pack_bf(float lo, float hi) {
    __nv_bfloat162 p = __floats2bfloat162_rn(lo, hi);
    return *(unsigned*)&p;
}

// ---------------- one-time setup ----------------
__global__ void cvt_all(
    const float* __restrict__ lmsg_w, const float* __restrict__ cmsg_w,
    const float* __restrict__ cu_wih, const float* __restrict__ cu_whh,
    const float* __restrict__ lu_wih, const float* __restrict__ lu_whh,
    const float* __restrict__ vote_w0, const float* __restrict__ vote_w1,
    bf16* __restrict__ wb)
{
    int i = blockIdx.x * 256 + threadIdx.x;
    if (i >= WB_TOTAL) return;
    float v;
    if      (i < WB_CMSG)   v = lmsg_w[i - WB_LMSG];
    else if (i < WB_CUWIH)  v = cmsg_w[i - WB_CMSG];
    else if (i < WB_CUWHH)  v = cu_wih[i - WB_CUWIH];
    else if (i < WB_LUWIH)  v = cu_whh[i - WB_CUWHH];
    else if (i < WB_LUWHH)  v = lu_wih[i - WB_LUWIH];
    else if (i < WB_VOTE0)  v = lu_whh[i - WB_LUWHH];
    else if (i < WB_VOTE1)  v = vote_w0[i - WB_VOTE0];
    else                    v = vote_w1[i - WB_VOTE1];
    wb[i] = __float2bfloat16_rn(v);
}

__global__ void init_hc(const float* __restrict__ Lw, const float* __restrict__ Lb,
                        const float* __restrict__ Cw, const float* __restrict__ Cb,
                        bf16* __restrict__ hl, bf16* __restrict__ hc,
                        float* __restrict__ cl, float* __restrict__ cc)
{
    int r = blockIdx.x, d = threadIdx.x;
    if (r < LROWS) {
        hl[(size_t)r * D + d] = __float2bfloat16_rn(Lw[d] + Lb[d]);
        cl[(size_t)r * D + d] = 0.f;
    }
    hc[(size_t)r * D + d] = __float2bfloat16_rn(Cw[d] + Cb[d]);
    cc[(size_t)r * D + d] = 0.f;
}

__global__ void compact_edges(const int* __restrict__ edge_src, int* __restrict__ esrc,
                              int* __restrict__ deg)
{
    int e = blockIdx.x * 256 + threadIdx.x;
    if (e < NEDGE) {
        int g = edge_src[e];
        esrc[e] = (g / NNG) * (2 * NVv) + (g % NNG);
    }
    if (e < LROWS) deg[e] = 0;
}

// atomic fill: slot order nondeterministic, fixed by sort pass below
__global__ void fill_adj(const int* __restrict__ esrc,
                         int* __restrict__ adj, int* __restrict__ deg)
{
    int e = blockIdx.x * 256 + threadIdx.x;
    if (e >= NEDGE) return;
    int lit = esrc[e];
    int slot = atomicAdd(&deg[lit], 1);
    if (slot < ADJW) adj[lit * ADJW + slot] = e / KLIT;
}

// canonicalize: clamp deg, sort each row ascending (deterministic adjacency)
__global__ void sort_adj(int* __restrict__ adj, int* __restrict__ deg)
{
    int lit = blockIdx.x * 256 + threadIdx.x;
    if (lit >= LROWS) return;
    int n = deg[lit];
    if (n > ADJW) n = ADJW;
    deg[lit] = n;
    int* a = adj + (size_t)lit * ADJW;
    for (int i = 1; i < n; i++) {
        int key = a[i], j = i - 1;
        while (j >= 0 && a[j] > key) { a[j + 1] = a[j]; j--; }
        a[j + 1] = key;
    }
}

// ---------------- fused MLP (bf16, cp.async W pipeline), BM=32, 256 thr -----------
#define MLP_SMEM ((32 * 68 + 2 * 128 * 68) * 4)
template<int NL>
__global__ __launch_bounds__(256) void mlp_fused(
    const bf16* __restrict__ hin,
    const bf16* __restrict__ W0, const float* __restrict__ B0,
    const bf16* __restrict__ W1, const float* __restrict__ B1,
    const bf16* __restrict__ W2, const float* __restrict__ B2,
    bf16* __restrict__ out, int relu_last)
{
    extern __shared__ __align__(16) unsigned char dynsmem[];
    unsigned (*X)[68] = (unsigned(*)[68])dynsmem;
    unsigned* Wbase   = (unsigned*)(dynsmem + 32 * 68 * 4);

    const int tid  = threadIdx.x;
    const int lane = tid & 31;
    const int warp = tid >> 5;
    const int grp  = lane >> 2;
    const int tig  = lane & 3;
    const int bm   = blockIdx.x * 32;

    const bf16* Wl[3] = { W0, W1, W2 };
    const float* Bl[3] = { B0, B1, B2 };

    {
        const bf16* W = Wl[0];
        #pragma unroll
        for (int t = 0; t < 8; t++) {
            int flat = tid + 256 * t;
            int n = flat >> 4, kb = flat & 15;
            cpasync16(Wbase + (size_t)n * 68 + kb * 4, W + (size_t)n * D + kb * 8);
        }
        CP_COMMIT();
    }
    #pragma unroll
    for (int t = 0; t < 2; t++) {
        int flat = tid + 256 * t;
        int r = flat >> 4, kb = flat & 15;
        uint4 v = *(const uint4*)(hin + (size_t)(bm + r) * D + kb * 8);
        *(uint4*)&X[r][kb * 4] = v;
    }

    for (int l = 0; l < NL; l++) {
        CP_WAIT0();
        __syncthreads();
        unsigned (*Wsm)[68] = (unsigned(*)[68])(Wbase + (l & 1) * 128 * 68);
        if (l + 1 < NL) {
            unsigned* nxt = Wbase + ((l + 1) & 1) * 128 * 68;
            const bf16* W = Wl[l + 1];
            #pragma unroll
            for (int t = 0; t < 8; t++) {
                int flat = tid + 256 * t;
                int n = flat >> 4, kb = flat & 15;
                cpasync16(nxt + (size_t)n * 68 + kb * 4, W + (size_t)n * D + kb * 8);
            }
            CP_COMMIT();
        }

        float acc[2][2][4];
        #pragma unroll
        for (int mi = 0; mi < 2; mi++)
            #pragma unroll
            for (int ni = 0; ni < 2; ni++)
                #pragma unroll
                for (int u = 0; u < 4; u++) acc[mi][ni][u] = 0.f;

        #pragma unroll
        for (int ks = 0; ks < 8; ks++) {
            int kk = ks * 8;
            unsigned a[2][4], b[2][2];
            #pragma unroll
            for (int mi = 0; mi < 2; mi++) {
                int r = mi * 16 + grp;
                a[mi][0] = X[r    ][kk + tig];
                a[mi][1] = X[r + 8][kk + tig];
                a[mi][2] = X[r    ][kk + tig + 4];
                a[mi][3] = X[r + 8][kk + tig + 4];
            }
            #pragma unroll
            for (int ni = 0; ni < 2; ni++) {
                int n = warp * 16 + ni * 8 + grp;
                b[ni][0] = Wsm[n][kk + tig];
                b[ni][1] = Wsm[n][kk + tig + 4];
            }
            #pragma unroll
            for (int mi = 0; mi < 2; mi++)
                #pragma unroll
                for (int ni = 0; ni < 2; ni++)
                    mma_bf16(acc[mi][ni], a[mi][0], a[mi][1], a[mi][2], a[mi][3],
                             b[ni][0], b[ni][1]);
        }
        __syncthreads();

        const float* B = Bl[l];
        int do_relu = (l < NL - 1) || relu_last;
        #pragma unroll
        for (int mi = 0; mi < 2; mi++) {
            #pragma unroll
            for (int ni = 0; ni < 2; ni++) {
                int r0 = mi * 16 + grp;
                int c0 = warp * 16 + ni * 8 + 2 * tig;
                #pragma unroll
                for (int h = 0; h < 2; h++) {
                    int r = r0 + h * 8;
                    float v0 = acc[mi][ni][h * 2 + 0] + B[c0];
                    float v1 = acc[mi][ni][h * 2 + 1] + B[c0 + 1];
                    if (do_relu) { v0 = fmaxf(v0, 0.f); v1 = fmaxf(v1, 0.f); }
                    unsigned p = pack_bf(v0, v1);
                    if (l == NL - 1)
                        *(unsigned*)(out + (size_t)(bm + r) * D + c0) = p;
                    else
                        X[r][c0 >> 1] = p;
                }
            }
        }
    }
}

// ---------------- clause aggregation ----------------
__global__ void clause_agg(const bf16* __restrict__ msg, const int* __restrict__ esrc,
                           bf16* __restrict__ agg)
{
    int cr = blockIdx.x, d = threadIdx.x;
    const int* es = esrc + cr * KLIT;
    float s = 0.f;
    #pragma unroll
    for (int k = 0; k < KLIT; k++) s += __bfloat162float(msg[(size_t)es[k] * D + d]);
    agg[(size_t)cr * D + d] = __float2bfloat16_rn(s);
}

// ---------------- literal aggregation (ELL) ----------------
__global__ void lit_agg(const bf16* __restrict__ msg, const int* __restrict__ adj,
                        const int* __restrict__ deg, bf16* __restrict__ agg)
{
    int r = blockIdx.x, d = threadIdx.x;
    int n = deg[r];
    float s = 0.f;
    for (int t = 0; t < n; t++)
        s += __bfloat162float(msg[(size_t)adj[r * ADJW + t] * D + d]);
    agg[(size_t)r * D + d] = __float2bfloat16_rn(s);
}

// ---------------- fused gate GEMM (bf16, double-buffered) + LSTM epilogue ----------
#define GATE_STAGE ((64 * 36 + 128 * 36) * 4)
#define GATE_SMEM  (2 * GATE_STAGE)
template<int KTOT, int MODE>
__global__ __launch_bounds__(256) void gate_lstm(
    const bf16* __restrict__ agg, const bf16* __restrict__ hold,
    const bf16* __restrict__ Wih, int ldwih,
    const bf16* __restrict__ Whh,
    const float* __restrict__ bih, const float* __restrict__ bhh,
    bf16* __restrict__ hnew, float* __restrict__ cst)
{
    extern __shared__ __align__(16) unsigned char dynsmem[];

    const int tid  = threadIdx.x;
    const int lane = tid & 31;
    const int warp = tid >> 5;
    const int wr   = warp & 1;
    const int wc   = warp >> 1;
    const int grp  = lane >> 2;
    const int tig  = lane & 3;
    const int bm   = blockIdx.x * 64;
    const int dd0  = blockIdx.y * 32;

    float acc[2][4][4];
    #pragma unroll
    for (int mi = 0; mi < 2; mi++)
        #pragma unroll
        for (int ni = 0; ni < 4; ni++)
            #pragma unroll
            for (int u = 0; u < 4; u++) acc[mi][ni][u] = 0.f;

    auto ldA = [&](int ch, int t) -> uint4 {
        int k0 = ch * 64;
        int flat = tid + 256 * t;
        int lr = flat >> 3, kb = flat & 7;
        int row = bm + lr;
        int k = k0 + kb * 8;
        if (MODE == 0) {
            if (k0 < 128) return *(const uint4*)(agg  + (size_t)row * D + k);
            else          return *(const uint4*)(hold + (size_t)row * D + (k - 128));
        } else {
            if (k0 < 128)      return *(const uint4*)(agg  + (size_t)row * D + k);
            else if (k0 < 256) return *(const uint4*)(hold + (size_t)fliprow(row) * D + (k - 128));
            else               return *(const uint4*)(hold + (size_t)row * D + (k - 256));
        }
    };
    auto ldW = [&](int ch, int t) -> uint4 {
        int k0 = ch * 64;
        int flat = tid + 256 * t;
        int wrow = flat >> 3, kb = flat & 7;
        int n = (wrow >> 5) * 128 + dd0 + (wrow & 31);
        int k = k0 + kb * 8;
        if (k0 < KTOT - 128) return *(const uint4*)(Wih + (size_t)n * ldwih + k);
        else                 return *(const uint4*)(Whh + (size_t)n * D + (k - (KTOT - 128)));
    };
    auto stA = [&](int st, int t, uint4 v) {
        unsigned (*As)[36] = (unsigned(*)[36])(dynsmem + st * GATE_STAGE);
        int flat = tid + 256 * t;
        int lr = flat >> 3, kb = flat & 7;
        *(uint4*)&As[lr][kb * 4] = v;
    };
    auto stW = [&](int st, int t, uint4 v) {
        unsigned (*Ws)[36] = (unsigned(*)[36])(dynsmem + st * GATE_STAGE + 64 * 36 * 4);
        int flat = tid + 256 * t;
        int wrow = flat >> 3, kb = flat & 7;
        *(uint4*)&Ws[wrow][kb * 4] = v;
    };

    const int NCH = KTOT / 64;
    #pragma unroll
    for (int t = 0; t < 2; t++) stA(0, t, ldA(0, t));
    #pragma unroll
    for (int t = 0; t < 4; t++) stW(0, t, ldW(0, t));
    __syncthreads();

    for (int ch = 0; ch < NCH; ch++) {
        int st = ch & 1;
        uint4 pa[2], pw[4];
        bool more = (ch + 1 < NCH);
        if (more) {
            #pragma unroll
            for (int t = 0; t < 2; t++) pa[t] = ldA(ch + 1, t);
            #pragma unroll
            for (int t = 0; t < 4; t++) pw[t] = ldW(ch + 1, t);
        }
        unsigned (*As)[36] = (unsigned(*)[36])(dynsmem + st * GATE_STAGE);
        unsigned (*Ws)[36] = (unsigned(*)[36])(dynsmem + st * GATE_STAGE + 64 * 36 * 4);
        #pragma unroll
        for (int ks = 0; ks < 4; ks++) {
            unsigned a[2][4], b[4][2];
            #pragma unroll
            for (int mi = 0; mi < 2; mi++) {
                int r = wr * 32 + mi * 16 + grp;
                a[mi][0] = As[r    ][ks * 8 + tig];
                a[mi][1] = As[r + 8][ks * 8 + tig];
                a[mi][2] = As[r    ][ks * 8 + tig + 4];
                a[mi][3] = As[r + 8][ks * 8 + tig + 4];
            }
            #pragma unroll
            for (int ni = 0; ni < 4; ni++) {
                int n = wc * 32 + ni * 8 + grp;
                b[ni][0] = Ws[n][ks * 8 + tig];
                b[ni][1] = Ws[n][ks * 8 + tig + 4];
            }
            #pragma unroll
            for (int mi = 0; mi < 2; mi++)
                #pragma unroll
                for (int ni = 0; ni < 4; ni++)
                    mma_bf16(acc[mi][ni], a[mi][0], a[mi][1], a[mi][2], a[mi][3],
                             b[ni][0], b[ni][1]);
        }
        if (more) {
            #pragma unroll
            for (int t = 0; t < 2; t++) stA(1 - st, t, pa[t]);
            #pragma unroll
            for (int t = 0; t < 4; t++) stW(1 - st, t, pw[t]);
        }
        __syncthreads();
    }

    float (*gbuf)[132] = (float(*)[132])dynsmem;
    #pragma unroll
    for (int mi = 0; mi < 2; mi++) {
        #pragma unroll
        for (int ni = 0; ni < 4; ni++) {
            int r0 = wr * 32 + mi * 16 + grp;
            int c0 = wc * 32 + ni * 8 + 2 * tig;
            gbuf[r0    ][c0    ] = acc[mi][ni][0];
            gbuf[r0    ][c0 + 1] = acc[mi][ni][1];
            gbuf[r0 + 8][c0    ] = acc[mi][ni][2];
            gbuf[r0 + 8][c0 + 1] = acc[mi][ni][3];
        }
    }
    __syncthreads();

    int ddl = tid & 31;
    int rl0 = tid >> 5;
    int dd  = dd0 + ddl;
    float bi0 = bih[0 * 128 + dd] + bhh[0 * 128 + dd];
    float bi1 = bih[1 * 128 + dd] + bhh[1 * 128 + dd];
    float bi2 = bih[2 * 128 + dd] + bhh[2 * 128 + dd];
    float bi3 = bih[3 * 128 + dd] + bhh[3 * 128 + dd];
    #pragma unroll
    for (int it = 0; it < 8; it++) {
        int lrow = it * 8 + rl0;
        int row  = bm + lrow;
        float gi = gbuf[lrow][0 * 32 + ddl] + bi0;
        float gf = gbuf[lrow][1 * 32 + ddl] + bi1;
        float gg = gbuf[lrow][2 * 32 + ddl] + bi2;
        float go = gbuf[lrow][3 * 32 + ddl] + bi3;
        size_t off = (size_t)row * D + dd;
        float c2 = sigm(gf) * cst[off] + sigm(gi) * tanhf(gg);
        cst[off] = c2;
        hnew[off] = __float2bfloat16_rn(sigm(go) * tanhf(c2));
    }
}

// ---------------- vote head ----------------
__global__ void vote_row(const bf16* __restrict__ v2, const float* __restrict__ w2,
                         const float* __restrict__ b2, float* __restrict__ vrow)
{
    int r = blockIdx.x, t = threadIdx.x;
    float p = __bfloat162float(v2[(size_t)r * D + t]) * w2[t];
    #pragma unroll
    for (int s = 16; s > 0; s >>= 1) p += __shfl_down_sync(0xffffffff, p, s);
    __shared__ float ws[4];
    if ((t & 31) == 0) ws[t >> 5] = p;
    __syncthreads();
    if (t == 0) vrow[r] = ws[0] + ws[1] + ws[2] + ws[3] + b2[0];
}

__global__ void graph_mean(const float* __restrict__ vrow, const int* __restrict__ n_vars,
                           float* __restrict__ out)
{
    int g = blockIdx.x, t = threadIdx.x;
    float s = 0.f;
    for (int i = t; i < 2 * NVv; i += 256) s += vrow[g * (2 * NVv) + i];
    __shared__ float red[256];
    red[t] = s;
    __syncthreads();
    for (int st = 128; st > 0; st >>= 1) {
        if (t < st) red[t] += red[t + st];
        __syncthreads();
    }
    if (t == 0) out[g] = red[0] / (2.f * (float)n_vars[g]);
}

// ---------------- host orchestration ----------------
extern "C" void kernel_launch(void* const* d_in, const int* in_sizes, int n_in,
                              void* d_out, int out_size)
{
    const int* edge_src   = (const int*)d_in[0];
    const int* n_vars     = (const int*)d_in[6];
    const float* L_init_w = (const float*)d_in[7];
    const float* L_init_b = (const float*)d_in[8];
    const float* C_init_w = (const float*)d_in[9];
    const float* C_init_b = (const float*)d_in[10];
    const float* lmsg_w   = (const float*)d_in[11];
    const float* lmsg_b   = (const float*)d_in[12];
    const float* cmsg_w   = (const float*)d_in[13];
    const float* cmsg_b   = (const float*)d_in[14];
    const float* lu_wih   = (const float*)d_in[15];
    const float* lu_whh   = (const float*)d_in[16];
    const float* lu_bih   = (const float*)d_in[17];
    const float* lu_bhh   = (const float*)d_in[18];
    const float* cu_wih   = (const float*)d_in[19];
    const float* cu_whh   = (const float*)d_in[20];
    const float* cu_bih   = (const float*)d_in[21];
    const float* cu_bhh   = (const float*)d_in[22];
    const float* vote_w0  = (const float*)d_in[23];
    const float* vote_b0  = (const float*)d_in[24];
    const float* vote_w1  = (const float*)d_in[25];
    const float* vote_b1  = (const float*)d_in[26];
    const float* vote_w2  = (const float*)d_in[27];
    const float* vote_b2  = (const float*)d_in[28];

    bf16 *hl0, *hl1, *hc0, *hc1, *msg, *agg, *wb;
    float *cl, *cc, *vrow;
    int *esrc, *adj, *deg;
    cudaGetSymbolAddress((void**)&hl0,  d_hl);      hl1 = hl0 + LROWS * D;
    cudaGetSymbolAddress((void**)&hc0,  d_hc);      hc1 = hc0 + CROWS * D;
    cudaGetSymbolAddress((void**)&cl,   d_cl);
    cudaGetSymbolAddress((void**)&cc,   d_cc);
    cudaGetSymbolAddress((void**)&msg,  d_msg);
    cudaGetSymbolAddress((void**)&agg,  d_agg);
    cudaGetSymbolAddress((void**)&wb,   d_wb);
    cudaGetSymbolAddress((void**)&esrc, d_esrc);
    cudaGetSymbolAddress((void**)&adj,  d_adj);
    cudaGetSymbolAddress((void**)&deg,  d_deg);
    cudaGetSymbolAddress((void**)&vrow, d_vrow);

    cudaFuncSetAttribute(mlp_fused<3>, cudaFuncAttributeMaxDynamicSharedMemorySize, MLP_SMEM);
    cudaFuncSetAttribute(mlp_fused<2>, cudaFuncAttributeMaxDynamicSharedMemorySize, MLP_SMEM);
    cudaFuncSetAttribute(gate_lstm<256, 0>, cudaFuncAttributeMaxDynamicSharedMemorySize, GATE_SMEM);
    cudaFuncSetAttribute(gate_lstm<384, 1>, cudaFuncAttributeMaxDynamicSharedMemorySize, GATE_SMEM);

    cvt_all<<<(WB_TOTAL + 255) / 256, 256>>>(lmsg_w, cmsg_w, cu_wih, cu_whh,
                                             lu_wih, lu_whh, vote_w0, vote_w1, wb);
    compact_edges<<<(NEDGE + 255) / 256, 256>>>(edge_src, esrc, deg);
    init_hc<<<CROWS, D>>>(L_init_w, L_init_b, C_init_w, C_init_b, hl0, hc0, cl, cc);
    fill_adj<<<(NEDGE + 255) / 256, 256>>>(esrc, adj, deg);
    sort_adj<<<(LROWS + 255) / 256, 256>>>(adj, deg);

    bf16* hls[2] = { hl0, hl1 };
    bf16* hcs[2] = { hc0, hc1 };

    for (int r = 0; r < ROUNDS; r++) {
        bf16* hlc = hls[r & 1];
        bf16* hln = hls[(r + 1) & 1];
        bf16* hcc = hcs[r & 1];
        bf16* hcn = hcs[(r + 1) & 1];

        mlp_fused<3><<<LROWS / 32, 256, MLP_SMEM>>>(hlc,
            wb + WB_LMSG + 0 * D * D, lmsg_b + 0 * D,
            wb + WB_LMSG + 1 * D * D, lmsg_b + 1 * D,
            wb + WB_LMSG + 2 * D * D, lmsg_b + 2 * D, msg, 0);
        clause_agg<<<CROWS, D>>>(msg, esrc, agg);
        gate_lstm<256, 0><<<dim3(CROWS / 64, 4), 256, GATE_SMEM>>>(agg, hcc,
            wb + WB_CUWIH, D, wb + WB_CUWHH, cu_bih, cu_bhh, hcn, cc);
        mlp_fused<3><<<CROWS / 32, 256, MLP_SMEM>>>(hcn,
            wb + WB_CMSG + 0 * D * D, cmsg_b + 0 * D,
            wb + WB_CMSG + 1 * D * D, cmsg_b + 1 * D,
            wb + WB_CMSG + 2 * D * D, cmsg_b + 2 * D, msg, 0);
        lit_agg<<<LROWS, D>>>(msg, adj, deg, agg);
        gate_lstm<384, 1><<<dim3(LROWS / 64, 4), 256, GATE_SMEM>>>(agg, hlc,
            wb + WB_LUWIH, 2 * D, wb + WB_LUWHH, lu_bih, lu_bhh, hln, cl);
    }

    bf16* hfin = hls[ROUNDS & 1];
    mlp_fused<2><<<LROWS / 32, 256, MLP_SMEM>>>(hfin,
        wb + WB_VOTE0, vote_b0, wb + WB_VOTE1, vote_b1, wb + WB_VOTE1, vote_b1, msg, 1);
    vote_row<<<LROWS, D>>>(msg, vote_w2, vote_b2, vrow);
    graph_mean<<<NGg, 256>>>(vrow, n_vars, (float*)d_out);

    (void)in_sizes; (void)n_in; (void)out_size;
}